// round 3
// baseline (speedup 1.0000x reference)
#include <cuda_runtime.h>

// ---------------------------------------------------------------------------
// Single-pass decoupled look-back inclusive prefix sum (fp32).
//
// - Tile = 512 data threads x 16 items = 8192 elements (4096 tiles for 2^25).
// - 17th warp (threads 512..543) is a dedicated look-back warp that polls
//   predecessor descriptors concurrently with the data warps' loads/scans.
// - Descriptors packed u64: [value:f32 << 32 | flag:u32]
//   flag: 0 invalid, 1 aggregate, 2 inclusive prefix.
// - Small init kernel resets descriptors + counter each launch (device
//   globals persist across graph replays).
// ---------------------------------------------------------------------------

#define DATA_THREADS 512
#define ALL_THREADS  544           // 512 data + 32 look-back
#define ITEMS        16
#define TILE_ELEMS   (DATA_THREADS * ITEMS)   // 8192
#define NWARPS       (DATA_THREADS / 32)      // 16
#define MAX_TILES    8192

#define FLAG_INVALID 0u
#define FLAG_AGG     1u
#define FLAG_PREFIX  2u

__device__ unsigned long long g_desc[MAX_TILES];
__device__ unsigned int       g_counter;

static __device__ __forceinline__ unsigned long long
pack_desc(float v, unsigned flag) {
    return ((unsigned long long)__float_as_uint(v) << 32) | (unsigned long long)flag;
}

static __device__ __forceinline__ unsigned long long
ld_relaxed_u64(const unsigned long long* p) {
    unsigned long long v;
    asm volatile("ld.relaxed.gpu.u64 %0, [%1];" : "=l"(v) : "l"(p) : "memory");
    return v;
}

static __device__ __forceinline__ void
st_relaxed_u64(unsigned long long* p, unsigned long long v) {
    asm volatile("st.relaxed.gpu.u64 [%0], %1;" :: "l"(p), "l"(v) : "memory");
}

__global__ void scan_init_kernel(int num_tiles) {
    int i = blockIdx.x * blockDim.x + threadIdx.x;
    if (i < num_tiles) g_desc[i] = 0ull;
    if (i == 0) g_counter = 0u;
}

__global__ __launch_bounds__(ALL_THREADS, 3)
void scan_kernel(const float* __restrict__ x, float* __restrict__ out,
                 int n, int num_tiles) {
    __shared__ unsigned int    s_tile;
    __shared__ float           s_warp[NWARPS];
    __shared__ volatile float  s_bsum;
    __shared__ volatile int    s_bsum_flag;
    __shared__ volatile float  s_excl;
    __shared__ volatile int    s_excl_flag;

    const int tid  = threadIdx.x;
    const int lane = tid & 31;
    const unsigned FULL = 0xffffffffu;

    if (tid == 0) {
        s_bsum_flag = 0;
        s_excl_flag = 0;
        s_tile = atomicAdd(&g_counter, 1u);
    }
    __syncthreads();

    const int tile = (int)s_tile;
    const int base = tile * TILE_ELEMS;

    if (tid >= DATA_THREADS) {
        // ===================== Look-back warp ==============================
        // Runs concurrently with the data warps' loads/scans.
        float running = 0.0f;
        if (tile > 0) {
            int pred = tile - 1;
            while (true) {
                int idx = pred - lane;            // lane 0 = nearest predecessor
                float    val = 0.0f;
                unsigned fl  = FLAG_PREFIX;
                bool     valid;
                do {
                    if (idx >= 0) {
                        unsigned long long d = ld_relaxed_u64(&g_desc[idx]);
                        fl    = (unsigned)(d & 0xffffffffull);
                        val   = __uint_as_float((unsigned)(d >> 32));
                        valid = (fl != FLAG_INVALID);
                    } else {
                        valid = true; fl = FLAG_PREFIX; val = 0.0f;
                    }
                    if (!valid) __nanosleep(40);
                } while (__any_sync(FULL, !valid));

                unsigned pb = __ballot_sync(FULL, fl == FLAG_PREFIX);
                float contrib;
                if (pb) {
                    int p = __ffs(pb) - 1;        // closest PREFIX wins
                    contrib = (lane <= p) ? val : 0.0f;
                } else {
                    contrib = val;                // 32 aggregates, keep walking
                }
                #pragma unroll
                for (int d2 = 16; d2; d2 >>= 1)
                    contrib += __shfl_xor_sync(FULL, contrib, d2);
                running += contrib;

                if (pb) break;
                pred -= 32;
            }
        }
        // Wait for the data side's block_sum, then publish PREFIX.
        while (s_bsum_flag == 0) { }
        __threadfence();                  // order: AGG store (other thread) < PREFIX store
        float bs = s_bsum;
        if (lane == 0) {
            st_relaxed_u64(&g_desc[tile], pack_desc(running + bs, FLAG_PREFIX));
            s_excl = running;
        }
        __threadfence_block();
        if (lane == 0) s_excl_flag = 1;
    } else {
        // ===================== Data warps ==================================
        const int warp = tid >> 5;

        float r[ITEMS];
        const bool full_tile = (base + TILE_ELEMS) <= n;
        if (full_tile) {
            const float4* p = reinterpret_cast<const float4*>(x + base);
            #pragma unroll
            for (int i = 0; i < 4; i++) {
                float4 a = p[tid * 4 + i];
                r[i * 4 + 0] = a.x;
                r[i * 4 + 1] = a.y;
                r[i * 4 + 2] = a.z;
                r[i * 4 + 3] = a.w;
            }
        } else {
            #pragma unroll
            for (int j = 0; j < ITEMS; j++) {
                int e = base + tid * ITEMS + j;
                r[j] = (e < n) ? x[e] : 0.0f;
            }
        }

        // Per-thread inclusive scan
        float run = 0.0f;
        #pragma unroll
        for (int j = 0; j < ITEMS; j++) { run += r[j]; r[j] = run; }
        const float tsum = run;

        // Warp scan of per-thread sums
        float ws = tsum;
        #pragma unroll
        for (int d = 1; d < 32; d <<= 1) {
            float t = __shfl_up_sync(FULL, ws, d);
            if (lane >= d) ws += t;
        }
        if (lane == 31) s_warp[warp] = ws;

        // Data-threads-only barrier (named barrier 1, 512 threads)
        asm volatile("bar.sync 1, %0;" :: "r"(DATA_THREADS) : "memory");

        if (warp == 0) {
            float w = (lane < NWARPS) ? s_warp[lane] : 0.0f;
            #pragma unroll
            for (int d = 1; d < 32; d <<= 1) {
                float t = __shfl_up_sync(FULL, w, d);
                if (lane >= d) w += t;
            }
            if (lane < NWARPS) s_warp[lane] = w;
        }
        asm volatile("bar.sync 1, %0;" :: "r"(DATA_THREADS) : "memory");

        const float block_sum   = s_warp[NWARPS - 1];
        const float warp_excl   = (warp == 0) ? 0.0f : s_warp[warp - 1];
        const float thread_excl = warp_excl + (ws - tsum);

        if (tid == 0) {
            // Publish aggregate first (unblocks successors' look-back chains),
            // fence, then hand block_sum to the look-back warp.
            st_relaxed_u64(&g_desc[tile], pack_desc(block_sum, FLAG_AGG));
            __threadfence();
            s_bsum = block_sum;
            __threadfence_block();
            s_bsum_flag = 1;
        }

        // Wait for the exclusive prefix from the look-back warp.
        while (s_excl_flag == 0) { }
        __threadfence_block();
        const float offset = s_excl + thread_excl;

        if (full_tile) {
            float4* o = reinterpret_cast<float4*>(out + base);
            #pragma unroll
            for (int i = 0; i < 4; i++) {
                float4 a;
                a.x = r[i * 4 + 0] + offset;
                a.y = r[i * 4 + 1] + offset;
                a.z = r[i * 4 + 2] + offset;
                a.w = r[i * 4 + 3] + offset;
                o[tid * 4 + i] = a;
            }
        } else {
            #pragma unroll
            for (int j = 0; j < ITEMS; j++) {
                int e = base + tid * ITEMS + j;
                if (e < n) out[e] = r[j] + offset;
            }
        }
    }
}

extern "C" void kernel_launch(void* const* d_in, const int* in_sizes, int n_in,
                              void* d_out, int out_size) {
    const float* x = (const float*)d_in[0];
    float* out     = (float*)d_out;
    const int n    = in_sizes[0];
    int num_tiles  = (n + TILE_ELEMS - 1) / TILE_ELEMS;
    if (num_tiles > MAX_TILES) num_tiles = MAX_TILES;  // n <= 64M by construction

    scan_init_kernel<<<(num_tiles + 255) / 256, 256>>>(num_tiles);
    scan_kernel<<<num_tiles, ALL_THREADS>>>(x, out, n, num_tiles);
}

// round 6
// speedup vs baseline: 1.2192x; 1.2192x over previous
#include <cuda_runtime.h>

// ---------------------------------------------------------------------------
// Single-pass decoupled look-back inclusive prefix sum (fp32).
// Proven R1 structure (block scan -> publish AGG -> warp-0 look-back ->
// publish PREFIX -> store), scaled to 16384-element tiles to shorten the
// inter-tile dependence chain (2048 tiles for 2^25 elements).
//
// Descriptors packed u64: [value:f32 << 32 | flag:u32]
//   flag: 0 = invalid, 1 = aggregate available, 2 = inclusive prefix.
// Packed word => relaxed 64-bit ld/st suffice (value travels with flag).
// ---------------------------------------------------------------------------

#define THREADS      1024
#define ITEMS        16
#define TILE_ELEMS   (THREADS * ITEMS)   // 16384
#define NWARPS       (THREADS / 32)      // 32
#define MAX_TILES    4096                // supports up to 64M elements

#define FLAG_INVALID 0u
#define FLAG_AGG     1u
#define FLAG_PREFIX  2u

__device__ unsigned long long g_desc[MAX_TILES];
__device__ unsigned int       g_counter;

static __device__ __forceinline__ unsigned long long
pack_desc(float v, unsigned flag) {
    return ((unsigned long long)__float_as_uint(v) << 32) | (unsigned long long)flag;
}

static __device__ __forceinline__ unsigned long long
ld_relaxed_u64(const unsigned long long* p) {
    unsigned long long v;
    asm volatile("ld.relaxed.gpu.u64 %0, [%1];" : "=l"(v) : "l"(p) : "memory");
    return v;
}

static __device__ __forceinline__ void
st_relaxed_u64(unsigned long long* p, unsigned long long v) {
    asm volatile("st.relaxed.gpu.u64 [%0], %1;" :: "l"(p), "l"(v) : "memory");
}

// Reset tile descriptors + tile counter (device globals persist across
// graph replays, so this must run before each scan).
__global__ void scan_init_kernel(int num_tiles) {
    int i = blockIdx.x * blockDim.x + threadIdx.x;
    if (i < num_tiles) g_desc[i] = 0ull;
    if (i == 0) g_counter = 0u;
}

__global__ __launch_bounds__(THREADS)
void scan_kernel(const float* __restrict__ x, float* __restrict__ out, int n) {
    __shared__ unsigned int s_tile;
    __shared__ float        s_warp[NWARPS];
    __shared__ float        s_excl;

    const int tid  = threadIdx.x;
    const int lane = tid & 31;
    const int warp = tid >> 5;
    const unsigned FULL = 0xffffffffu;

    // Dynamic tile assignment: tiles are only ever owned by resident CTAs,
    // and every tile < ours was acquired earlier => look-back cannot deadlock.
    if (tid == 0) s_tile = atomicAdd(&g_counter, 1u);
    __syncthreads();
    const int tile = (int)s_tile;
    const int base = tile * TILE_ELEMS;

    // ---- Load 16 elements per thread (blocked, float4, streaming) ----------
    float r[ITEMS];
    const bool full_tile = (base + TILE_ELEMS) <= n;
    if (full_tile) {
        const float4* p = reinterpret_cast<const float4*>(x + base);
        #pragma unroll
        for (int i = 0; i < 4; i++) {
            float4 a = __ldcs(p + tid * 4 + i);   // streaming: spare L2 for descs
            r[i * 4 + 0] = a.x;
            r[i * 4 + 1] = a.y;
            r[i * 4 + 2] = a.z;
            r[i * 4 + 3] = a.w;
        }
    } else {
        #pragma unroll
        for (int j = 0; j < ITEMS; j++) {
            int e = base + tid * ITEMS + j;
            r[j] = (e < n) ? x[e] : 0.0f;
        }
    }

    // ---- Per-thread inclusive scan -----------------------------------------
    float run = 0.0f;
    #pragma unroll
    for (int j = 0; j < ITEMS; j++) { run += r[j]; r[j] = run; }
    const float tsum = run;

    // ---- Block scan of per-thread sums -------------------------------------
    float ws = tsum;
    #pragma unroll
    for (int d = 1; d < 32; d <<= 1) {
        float t = __shfl_up_sync(FULL, ws, d);
        if (lane >= d) ws += t;
    }
    if (lane == 31) s_warp[warp] = ws;
    __syncthreads();
    if (warp == 0) {
        float w = s_warp[lane];                   // NWARPS == 32, full warp
        #pragma unroll
        for (int d = 1; d < 32; d <<= 1) {
            float t = __shfl_up_sync(FULL, w, d);
            if (lane >= d) w += t;
        }
        s_warp[lane] = w;
    }
    __syncthreads();

    const float block_sum   = s_warp[NWARPS - 1];
    const float warp_excl   = (warp == 0) ? 0.0f : s_warp[warp - 1];
    const float thread_excl = warp_excl + (ws - tsum);

    // ---- Publish this tile's status ----------------------------------------
    if (tid == 0) {
        unsigned flag = (tile == 0) ? FLAG_PREFIX : FLAG_AGG;
        st_relaxed_u64(&g_desc[tile], pack_desc(block_sum, flag));
        if (tile == 0) s_excl = 0.0f;
    }

    // ---- Warp-parallel decoupled look-back (warp 0) ------------------------
    if (warp == 0 && tile > 0) {
        float running = 0.0f;
        int pred = tile - 1;
        while (true) {
            int idx = pred - lane;       // lane 0 = nearest predecessor
            unsigned long long d;
            unsigned fl;
            bool valid;
            do {
                if (idx >= 0) {
                    d  = ld_relaxed_u64(&g_desc[idx]);
                    fl = (unsigned)(d & 0xffffffffull);
                    valid = (fl != FLAG_INVALID);
                } else {
                    d = pack_desc(0.0f, FLAG_PREFIX);
                    fl = FLAG_PREFIX;
                    valid = true;
                }
                if (!valid) __nanosleep(80);
            } while (__any_sync(FULL, !valid));

            float val = __uint_as_float((unsigned)(d >> 32));
            unsigned pb = __ballot_sync(FULL, fl == FLAG_PREFIX);

            float contrib;
            if (pb) {
                int p = __ffs(pb) - 1;   // closest PREFIX wins
                contrib = (lane <= p) ? val : 0.0f;
            } else {
                contrib = val;           // all 32 are aggregates, keep walking
            }
            #pragma unroll
            for (int d2 = 16; d2; d2 >>= 1)
                contrib += __shfl_xor_sync(FULL, contrib, d2);
            running += contrib;

            if (pb) break;
            pred -= 32;
        }
        if (lane == 0) {
            st_relaxed_u64(&g_desc[tile], pack_desc(running + block_sum, FLAG_PREFIX));
            s_excl = running;
        }
    }
    __syncthreads();

    // ---- Apply offsets and store -------------------------------------------
    const float offset = s_excl + thread_excl;
    if (full_tile) {
        float4* o = reinterpret_cast<float4*>(out + base);
        #pragma unroll
        for (int i = 0; i < 4; i++) {
            float4 a;
            a.x = r[i * 4 + 0] + offset;
            a.y = r[i * 4 + 1] + offset;
            a.z = r[i * 4 + 2] + offset;
            a.w = r[i * 4 + 3] + offset;
            __stcs(o + tid * 4 + i, a);           // streaming store
        }
    } else {
        #pragma unroll
        for (int j = 0; j < ITEMS; j++) {
            int e = base + tid * ITEMS + j;
            if (e < n) out[e] = r[j] + offset;
        }
    }
}

extern "C" void kernel_launch(void* const* d_in, const int* in_sizes, int n_in,
                              void* d_out, int out_size) {
    const float* x = (const float*)d_in[0];
    float* out     = (float*)d_out;
    const int n    = in_sizes[0];
    int num_tiles  = (n + TILE_ELEMS - 1) / TILE_ELEMS;
    if (num_tiles > MAX_TILES) num_tiles = MAX_TILES;  // n <= 64M by construction

    scan_init_kernel<<<(num_tiles + 255) / 256, 256>>>(num_tiles);
    scan_kernel<<<num_tiles, THREADS>>>(x, out, n);
}